// round 5
// baseline (speedup 1.0000x reference)
#include <cuda_runtime.h>
#include <stdint.h>

#define NN 262144
#define SCAN_BS 512
#define SCAN_NB 512   // NN / SCAN_BS

// ---------------- device scratch (static, no allocation) ----------------
__device__ int   g_deg[4 * NN];
__device__ int   g_ptr[4][NN + 1];
__device__ int   g_cnt[4][NN];
__device__ int   g_bsum[4][SCAN_NB];
__device__ int   g_src[4][4000000];     // gg needs 4M, others 2M
__device__ float g_wh[2000000];         // reordered hist edge weights
__device__ float g_dinv_gg[NN], g_dinv_ss[NN];
__device__ float g_x8a[NN * 8], g_x8b[NN * 8], g_x8c[NN * 8];  // padded 5->8 dims
__device__ float g_gx[NN * 64];         // game_x
__device__ float g_agg[NN * 64];        // aggregation scratch
__device__ float g_s0[NN * 64], g_s1[NN * 64], g_s2[NN * 64], g_s3[NN * 64];

// compile-time buffer pick (no pointer tables, no symbol lookups)
__device__ __forceinline__ const float* pick64(int i) {
    switch (i) {
        case 3: return g_gx;
        case 4: return g_agg;
        case 5: return g_s0;
        case 6: return g_s1;
        case 7: return g_s2;
        default: return g_s3;
    }
}
__device__ __forceinline__ float* pick64w(int i) {
    switch (i) {
        case 4: return g_agg;
        case 6: return g_s1;
        case 7: return g_s2;
        default: return g_s3;
    }
}
__device__ __forceinline__ const float* pick8(int i) {
    switch (i) {
        case 0: return g_x8a;
        case 1: return g_x8b;
        default: return g_x8c;
    }
}
__device__ __forceinline__ float* pick8w(int i) {
    switch (i) {
        case 1: return g_x8b;
        default: return g_x8c;
    }
}

// ---------------- CSR build (edges are INT32: JAX x64-disabled downgrades int64) ----
__global__ void k_zero_deg() {
    int i = blockIdx.x * blockDim.x + threadIdx.x;
    if (i < 4 * NN) g_deg[i] = 0;
}

__global__ void k_count(const int* __restrict__ ei, int E, int gi) {
    int i = blockIdx.x * blockDim.x + threadIdx.x;
    if (i < E) atomicAdd(&g_deg[gi * NN + ei[E + i]], 1);
}

__global__ void k_scan1(int gi) {
    __shared__ int s[SCAN_BS];
    int tid = threadIdx.x;
    int i = blockIdx.x * SCAN_BS + tid;
    int v = g_deg[gi * NN + i];
    s[tid] = v;
    __syncthreads();
    for (int off = 1; off < SCAN_BS; off <<= 1) {
        int t = (tid >= off) ? s[tid - off] : 0;
        __syncthreads();
        s[tid] += t;
        __syncthreads();
    }
    g_ptr[gi][i] = s[tid] - v;  // exclusive within block
    if (tid == SCAN_BS - 1) g_bsum[gi][blockIdx.x] = s[tid];
}

__global__ void k_scan2(int gi) {
    __shared__ int s[SCAN_NB];
    int tid = threadIdx.x;
    int v = g_bsum[gi][tid];
    s[tid] = v;
    __syncthreads();
    for (int off = 1; off < SCAN_NB; off <<= 1) {
        int t = (tid >= off) ? s[tid - off] : 0;
        __syncthreads();
        s[tid] += t;
        __syncthreads();
    }
    g_bsum[gi][tid] = s[tid] - v;  // exclusive
}

__global__ void k_scan3(int gi, int E) {
    int tid = threadIdx.x;
    int i = blockIdx.x * SCAN_BS + tid;
    int v = g_ptr[gi][i] + g_bsum[gi][blockIdx.x];
    g_ptr[gi][i] = v;
    g_cnt[gi][i] = v;
    if (i == 0) g_ptr[gi][NN] = E;
}

template <int HASW>
__global__ void k_fill(const int* __restrict__ ei, int E, int gi,
                       const float* __restrict__ ea) {
    int i = blockIdx.x * blockDim.x + threadIdx.x;
    if (i < E) {
        int r = ei[i];
        int c = ei[E + i];
        int p = atomicAdd(&g_cnt[gi][c], 1);
        g_src[gi][p] = r;
        if (HASW) g_wh[p] = ea[i];
    }
}

__global__ void k_dinv() {
    int i = blockIdx.x * blockDim.x + threadIdx.x;
    if (i < NN) {
        int dg = g_ptr[0][i + 1] - g_ptr[0][i];
        g_dinv_gg[i] = (dg > 0) ? rsqrtf((float)dg) : 0.f;
        int ds = g_ptr[3][i + 1] - g_ptr[3][i];
        g_dinv_ss[i] = (ds > 0) ? rsqrtf((float)ds) : 0.f;
    }
}

// ---------------- TAG1 (5-dim, padded to 8) ----------------
__global__ void k_pad(const float* __restrict__ x) {
    int i = blockIdx.x * blockDim.x + threadIdx.x;
    if (i < NN) {
        const float* r = x + (size_t)i * 5;
        size_t o = (size_t)i * 8;
        *(float4*)(g_x8a + o)     = make_float4(r[0], r[1], r[2], r[3]);
        *(float4*)(g_x8a + o + 4) = make_float4(r[4], 0.f, 0.f, 0.f);
    }
}

// one normalized hop in 5-dim space (thread per dst)
__global__ void k_hop5(int in_i, int out_i) {
    const float* __restrict__ x8 = pick8(in_i);
    float* __restrict__ y8 = pick8w(out_i);
    int d = blockIdx.x * blockDim.x + threadIdx.x;
    if (d >= NN) return;
    int beg = g_ptr[0][d], end = g_ptr[0][d + 1];
    float a0 = 0, a1 = 0, a2 = 0, a3 = 0, a4 = 0;
    for (int e = beg; e < end; e++) {
        int s = g_src[0][e];
        float w = g_dinv_gg[s];
        size_t o = (size_t)s * 8;
        float4 v = *(const float4*)(x8 + o);
        float v4 = x8[o + 4];
        a0 = fmaf(w, v.x, a0); a1 = fmaf(w, v.y, a1);
        a2 = fmaf(w, v.z, a2); a3 = fmaf(w, v.w, a3);
        a4 = fmaf(w, v4, a4);
    }
    float sd = g_dinv_gg[d];
    size_t o = (size_t)d * 8;
    *(float4*)(y8 + o)     = make_float4(a0 * sd, a1 * sd, a2 * sd, a3 * sd);
    *(float4*)(y8 + o + 4) = make_float4(a4 * sd, 0.f, 0.f, 0.f);
}

// gx = relu(x8a@W0 + x8b@W1 + x8c@W2 + b); W is (3,5,64)
__global__ void k_tag1(const float* __restrict__ W, const float* __restrict__ b) {
    __shared__ __align__(16) float sW[960];
    __shared__ __align__(16) float sb[64];
    __shared__ __align__(16) float sx[8][16];
    int tid = threadIdx.x;
    for (int i = tid; i < 960; i += 256) sW[i] = W[i];
    if (tid < 64) sb[tid] = b[tid];
    int ni = tid >> 5, tc = tid & 31;
    size_t node = (size_t)blockIdx.x * 8 + ni;
    if (tc < 5)       sx[ni][tc] = g_x8a[node * 8 + tc];
    else if (tc < 10) sx[ni][tc] = g_x8b[node * 8 + (tc - 5)];
    else if (tc < 15) sx[ni][tc] = g_x8c[node * 8 + (tc - 10)];
    __syncthreads();
    int c0 = 2 * tc;
    float a0 = sb[c0], a1 = sb[c0 + 1];
#pragma unroll
    for (int k = 0; k < 3; k++)
#pragma unroll
        for (int i = 0; i < 5; i++) {
            float xv = sx[ni][k * 5 + i];
            float2 w = *(const float2*)&sW[(k * 5 + i) * 64 + c0];
            a0 = fmaf(xv, w.x, a0);
            a1 = fmaf(xv, w.y, a1);
        }
    *(float2*)&g_gx[node * 64 + c0] = make_float2(fmaxf(a0, 0.f), fmaxf(a1, 0.f));
}

// ---------------- 64-dim hop (warp per dst) ----------------
// MODE 0: weighted sum (g_wh per edge). MODE 1: mean. MODE 2: sym-norm (g_dinv_ss).
template <int MODE>
__global__ void k_hop64(int in_i, int out_i, int gi) {
    const float* __restrict__ x = pick64(in_i);
    float* __restrict__ y = pick64w(out_i);
    int wid = (blockIdx.x * blockDim.x + threadIdx.x) >> 5;
    if (wid >= NN) return;
    int lane = threadIdx.x & 31;
    int beg = g_ptr[gi][wid], end = g_ptr[gi][wid + 1];
    float a0 = 0.f, a1 = 0.f;
    for (int e = beg; e < end; e++) {
        int s = g_src[gi][e];
        float w;
        if (MODE == 0)      w = g_wh[e];
        else if (MODE == 2) w = g_dinv_ss[s];
        else                w = 1.f;
        size_t o = (size_t)s * 64 + lane;
        a0 = fmaf(w, __ldg(x + o), a0);
        a1 = fmaf(w, __ldg(x + o + 32), a1);
    }
    float sc = 1.f;
    if (MODE == 1) { int c = end - beg; if (c > 0) sc = 1.f / (float)c; }
    if (MODE == 2) sc = g_dinv_ss[wid];
    y[(size_t)wid * 64 + lane]      = a0 * sc;
    y[(size_t)wid * 64 + 32 + lane] = a1 * sc;
}

// ---------------- GraphConv combine ----------------
// s0 = relu(g_agg@w_rel + b_rel + x_state@w_root)
__global__ void k_gc(const float* __restrict__ xs, const float* __restrict__ wrel,
                     const float* __restrict__ brel, const float* __restrict__ wroot) {
    __shared__ __align__(16) float sWr[4096];
    __shared__ __align__(16) float sWo[384];
    __shared__ __align__(16) float sb[64];
    __shared__ __align__(16) float sx[8][64];
    __shared__ __align__(16) float sxs[8][8];
    int tid = threadIdx.x;
    for (int i = tid; i < 4096; i += 256) sWr[i] = wrel[i];
    for (int i = tid; i < 384; i += 256) sWo[i] = wroot[i];
    if (tid < 64) sb[tid] = brel[tid];
    int ni = tid >> 5, tc = tid & 31;
    size_t node = (size_t)blockIdx.x * 8 + ni;
    sx[ni][tc]      = g_agg[node * 64 + tc];
    sx[ni][tc + 32] = g_agg[node * 64 + tc + 32];
    if (tc < 6) sxs[ni][tc] = xs[node * 6 + tc];
    __syncthreads();
    int c0 = 2 * tc;
    float a0 = sb[c0], a1 = sb[c0 + 1];
#pragma unroll 8
    for (int j = 0; j < 64; j++) {
        float xv = sx[ni][j];
        float2 w = *(const float2*)&sWr[j * 64 + c0];
        a0 = fmaf(xv, w.x, a0);
        a1 = fmaf(xv, w.y, a1);
    }
#pragma unroll
    for (int j = 0; j < 6; j++) {
        float xv = sxs[ni][j];
        float2 w = *(const float2*)&sWo[j * 64 + c0];
        a0 = fmaf(xv, w.x, a0);
        a1 = fmaf(xv, w.y, a1);
    }
    *(float2*)&g_s0[node * 64 + c0] = make_float2(fmaxf(a0, 0.f), fmaxf(a1, 0.f));
}

// ---------------- SAGE combine ----------------
// s0 = relu(g_agg@w_l + b_l + s0@w_r)   (in-place safe: per-node rows only)
__global__ void k_sage(const float* __restrict__ wl, const float* __restrict__ bl,
                       const float* __restrict__ wr) {
    __shared__ __align__(16) float sWl[4096];
    __shared__ __align__(16) float sWr2[4096];
    __shared__ __align__(16) float sb[64];
    __shared__ __align__(16) float sm[8][64];
    __shared__ __align__(16) float ss_[8][64];
    int tid = threadIdx.x;
    for (int i = tid; i < 4096; i += 256) { sWl[i] = wl[i]; sWr2[i] = wr[i]; }
    if (tid < 64) sb[tid] = bl[tid];
    int ni = tid >> 5, tc = tid & 31;
    size_t node = (size_t)blockIdx.x * 8 + ni;
    sm[ni][tc]       = g_agg[node * 64 + tc];
    sm[ni][tc + 32]  = g_agg[node * 64 + tc + 32];
    ss_[ni][tc]      = g_s0[node * 64 + tc];
    ss_[ni][tc + 32] = g_s0[node * 64 + tc + 32];
    __syncthreads();
    int c0 = 2 * tc;
    float a0 = sb[c0], a1 = sb[c0 + 1];
#pragma unroll 8
    for (int j = 0; j < 64; j++) {
        float mv = sm[ni][j];
        float2 w = *(const float2*)&sWl[j * 64 + c0];
        a0 = fmaf(mv, w.x, a0);
        a1 = fmaf(mv, w.y, a1);
        float sv = ss_[ni][j];
        float2 w2 = *(const float2*)&sWr2[j * 64 + c0];
        a0 = fmaf(sv, w2.x, a0);
        a1 = fmaf(sv, w2.y, a1);
    }
    *(float2*)&g_s0[node * 64 + c0] = make_float2(fmaxf(a0, 0.f), fmaxf(a1, 0.f));
}

// ---------------- TAG2 combine + final Linear (fused, <=48KB static smem) ----------------
// t = relu(s0@W0 + s1@W1 + s2@W2 + s3@W3 + b);  out = t@lin_w + lin_b
// Weights staged in two 32KB passes (W0,W1 then W2,W3).
__global__ void k_tag2(const float* __restrict__ W, const float* __restrict__ b,
                       const float* __restrict__ lw, const float* __restrict__ lb,
                       float* __restrict__ out) {
    __shared__ __align__(16) float sW[8192];      // 2 matrices of 64x64
    __shared__ __align__(16) float sLin[512];
    __shared__ __align__(16) float sb[64];
    __shared__ __align__(16) float slb[8];
    __shared__ __align__(16) float sx[8][256];    // per-node [s0|s1|s2|s3]
    __shared__ __align__(16) float st[8][64];
    int tid = threadIdx.x;
    for (int i = tid; i < 512; i += 256) sLin[i] = lw[i];
    if (tid < 64) sb[tid] = b[tid];
    if (tid < 8) slb[tid] = lb[tid];
    int ni = tid >> 5, tc = tid & 31;
    size_t node = (size_t)blockIdx.x * 8 + ni;
    sx[ni][tc]            = g_s0[node * 64 + tc];
    sx[ni][tc + 32]       = g_s0[node * 64 + tc + 32];
    sx[ni][64 + tc]       = g_s1[node * 64 + tc];
    sx[ni][64 + tc + 32]  = g_s1[node * 64 + tc + 32];
    sx[ni][128 + tc]      = g_s2[node * 64 + tc];
    sx[ni][128 + tc + 32] = g_s2[node * 64 + tc + 32];
    sx[ni][192 + tc]      = g_s3[node * 64 + tc];
    sx[ni][192 + tc + 32] = g_s3[node * 64 + tc + 32];
    __syncthreads();   // FIX: sb/slb/sLin/sx visible to ALL threads before any read

    int c0 = 2 * tc;
    float a0 = sb[c0], a1 = sb[c0 + 1];
#pragma unroll
    for (int stage = 0; stage < 2; stage++) {
        __syncthreads();   // previous sW use complete
        for (int i = tid; i < 8192; i += 256) sW[i] = W[stage * 8192 + i];
        __syncthreads();
#pragma unroll
        for (int kk = 0; kk < 2; kk++) {
            const float* wk = sW + kk * 4096;
            const float* xk = sx[ni] + (stage * 2 + kk) * 64;
#pragma unroll 8
            for (int j = 0; j < 64; j++) {
                float xv = xk[j];
                float2 w = *(const float2*)&wk[j * 64 + c0];
                a0 = fmaf(xv, w.x, a0);
                a1 = fmaf(xv, w.y, a1);
            }
        }
    }
    a0 = fmaxf(a0, 0.f);
    a1 = fmaxf(a1, 0.f);
    st[ni][c0] = a0;
    st[ni][c0 + 1] = a1;
    __syncwarp();
    if (tc < 8) {
        float acc = slb[tc];
#pragma unroll 8
        for (int j = 0; j < 64; j++) acc = fmaf(st[ni][j], sLin[j * 8 + tc], acc);
        out[node * 8 + tc] = acc;
    }
}

// ---------------- host launch (kernel launches ONLY) ----------------
extern "C" void kernel_launch(void* const* d_in, const int* in_sizes, int n_in,
                              void* d_out, int out_size) {
    const float* x_game     = (const float*)d_in[0];
    const float* x_state    = (const float*)d_in[1];
    const int* e_gg         = (const int*)d_in[2];   // int32! (JAX x64 disabled)
    const int* e_hist       = (const int*)d_in[3];
    const int* e_in         = (const int*)d_in[4];
    const int* e_ss         = (const int*)d_in[5];
    const float* ea_hist    = (const float*)d_in[6];
    const float* tag1_w     = (const float*)d_in[7];
    const float* tag1_b     = (const float*)d_in[8];
    const float* tag2_w     = (const float*)d_in[9];
    const float* tag2_b     = (const float*)d_in[10];
    const float* gc_w_rel   = (const float*)d_in[11];
    const float* gc_b_rel   = (const float*)d_in[12];
    const float* gc_w_root  = (const float*)d_in[13];
    const float* sage_w_l   = (const float*)d_in[14];
    const float* sage_b_l   = (const float*)d_in[15];
    const float* sage_w_r   = (const float*)d_in[16];
    const float* lin_w      = (const float*)d_in[17];
    const float* lin_b      = (const float*)d_in[18];

    int E[4] = { in_sizes[2] / 2, in_sizes[3] / 2, in_sizes[4] / 2, in_sizes[5] / 2 };
    const int* EI[4] = { e_gg, e_hist, e_in, e_ss };

    // ---- CSR build ----
    k_zero_deg<<<(4 * NN + 255) / 256, 256>>>();
    for (int i = 0; i < 4; i++)
        k_count<<<(E[i] + 255) / 256, 256>>>(EI[i], E[i], i);
    for (int i = 0; i < 4; i++) {
        k_scan1<<<SCAN_NB, SCAN_BS>>>(i);
        k_scan2<<<1, SCAN_NB>>>(i);
        k_scan3<<<SCAN_NB, SCAN_BS>>>(i, E[i]);
    }
    k_fill<0><<<(E[0] + 255) / 256, 256>>>(EI[0], E[0], 0, nullptr);
    k_fill<1><<<(E[1] + 255) / 256, 256>>>(EI[1], E[1], 1, ea_hist);
    k_fill<0><<<(E[2] + 255) / 256, 256>>>(EI[2], E[2], 2, nullptr);
    k_fill<0><<<(E[3] + 255) / 256, 256>>>(EI[3], E[3], 3, nullptr);
    k_dinv<<<(NN + 255) / 256, 256>>>();

    // ---- TAGConv1 (game graph, 5-dim propagation) ----
    k_pad<<<(NN + 255) / 256, 256>>>(x_game);
    k_hop5<<<(NN + 255) / 256, 256>>>(0, 1);   // x8a -> x8b
    k_hop5<<<(NN + 255) / 256, 256>>>(1, 2);   // x8b -> x8c
    k_tag1<<<NN / 8, 256>>>(tag1_w, tag1_b);

    // ---- GraphConv (hist, weighted) ----
    k_hop64<0><<<NN / 8, 256>>>(3, 4, 1);      // gx -> agg
    k_gc<<<NN / 8, 256>>>(x_state, gc_w_rel, gc_b_rel, gc_w_root);

    // ---- SAGEConv (in, mean) ----
    k_hop64<1><<<NN / 8, 256>>>(3, 4, 2);      // gx -> agg
    k_sage<<<NN / 8, 256>>>(sage_w_l, sage_b_l, sage_w_r);

    // ---- TAGConv2 (ss, 3 normalized hops) + fused final Linear ----
    k_hop64<2><<<NN / 8, 256>>>(5, 6, 3);      // s0 -> s1
    k_hop64<2><<<NN / 8, 256>>>(6, 7, 3);      // s1 -> s2
    k_hop64<2><<<NN / 8, 256>>>(7, 8, 3);      // s2 -> s3
    k_tag2<<<NN / 8, 256>>>(tag2_w, tag2_b, lin_w, lin_b, (float*)d_out);
}

// round 6
// speedup vs baseline: 1.4987x; 1.4987x over previous
#include <cuda_runtime.h>
#include <stdint.h>

#define NN 262144
#define SCAN_BS 512
#define SCAN_NB 512   // NN / SCAN_BS

// ---------------- device scratch (static, no allocation) ----------------
__device__ int   g_deg[4 * NN];
__device__ int   g_ptr[4][NN + 1];
__device__ int   g_cnt[4][NN];
__device__ int   g_bsum[4][SCAN_NB];
__device__ int   g_src[4][4000000];     // gg needs 4M, others 2M
__device__ float g_wh[2000000];         // reordered hist edge weights
__device__ float g_dinv_gg[NN], g_dinv_ss[NN];
__device__ float g_x8a[NN * 8], g_x8b[NN * 8], g_x8c[NN * 8];  // padded 5->8 dims
__device__ float g_gx[NN * 64];         // game_x
__device__ float g_agg[NN * 64];        // aggregation scratch
__device__ float g_s0[NN * 64], g_s1[NN * 64], g_s2[NN * 64], g_s3[NN * 64];

// ---------------- packed f32x2 helpers (Blackwell FFMA2 via PTX) ----------------
typedef unsigned long long ull;
__device__ __forceinline__ ull pack2(float lo, float hi) {
    ull r; asm("mov.b64 %0, {%1, %2};" : "=l"(r) : "f"(lo), "f"(hi)); return r;
}
__device__ __forceinline__ void unpack2(ull v, float& lo, float& hi) {
    asm("mov.b64 {%0, %1}, %2;" : "=f"(lo), "=f"(hi) : "l"(v));
}
__device__ __forceinline__ ull ffma2(ull a, ull b, ull c) {
    ull d; asm("fma.rn.f32x2 %0, %1, %2, %3;" : "=l"(d) : "l"(a), "l"(b), "l"(c));
    return d;
}

// compile-time buffer pick (no pointer tables, no symbol lookups)
__device__ __forceinline__ const float* pick64(int i) {
    switch (i) {
        case 3: return g_gx;
        case 4: return g_agg;
        case 5: return g_s0;
        case 6: return g_s1;
        case 7: return g_s2;
        default: return g_s3;
    }
}
__device__ __forceinline__ float* pick64w(int i) {
    switch (i) {
        case 4: return g_agg;
        case 6: return g_s1;
        case 7: return g_s2;
        default: return g_s3;
    }
}
__device__ __forceinline__ const float* pick8(int i) {
    switch (i) {
        case 0: return g_x8a;
        case 1: return g_x8b;
        default: return g_x8c;
    }
}
__device__ __forceinline__ float* pick8w(int i) {
    switch (i) {
        case 1: return g_x8b;
        default: return g_x8c;
    }
}

// ---------------- CSR build (edges are INT32) ----------------
__global__ void k_zero_deg() {
    int i = blockIdx.x * blockDim.x + threadIdx.x;
    if (i < 4 * NN) g_deg[i] = 0;
}

__global__ void k_count(const int* __restrict__ ei, int E, int gi) {
    int i = blockIdx.x * blockDim.x + threadIdx.x;
    if (i < E) atomicAdd(&g_deg[gi * NN + ei[E + i]], 1);
}

__global__ void k_scan1(int gi) {
    __shared__ int s[SCAN_BS];
    int tid = threadIdx.x;
    int i = blockIdx.x * SCAN_BS + tid;
    int v = g_deg[gi * NN + i];
    s[tid] = v;
    __syncthreads();
    for (int off = 1; off < SCAN_BS; off <<= 1) {
        int t = (tid >= off) ? s[tid - off] : 0;
        __syncthreads();
        s[tid] += t;
        __syncthreads();
    }
    g_ptr[gi][i] = s[tid] - v;
    if (tid == SCAN_BS - 1) g_bsum[gi][blockIdx.x] = s[tid];
}

__global__ void k_scan2(int gi) {
    __shared__ int s[SCAN_NB];
    int tid = threadIdx.x;
    int v = g_bsum[gi][tid];
    s[tid] = v;
    __syncthreads();
    for (int off = 1; off < SCAN_NB; off <<= 1) {
        int t = (tid >= off) ? s[tid - off] : 0;
        __syncthreads();
        s[tid] += t;
        __syncthreads();
    }
    g_bsum[gi][tid] = s[tid] - v;
}

__global__ void k_scan3(int gi, int E) {
    int tid = threadIdx.x;
    int i = blockIdx.x * SCAN_BS + tid;
    int v = g_ptr[gi][i] + g_bsum[gi][blockIdx.x];
    g_ptr[gi][i] = v;
    g_cnt[gi][i] = v;
    if (i == 0) g_ptr[gi][NN] = E;
}

template <int HASW>
__global__ void k_fill(const int* __restrict__ ei, int E, int gi,
                       const float* __restrict__ ea) {
    int i = blockIdx.x * blockDim.x + threadIdx.x;
    if (i < E) {
        int r = ei[i];
        int c = ei[E + i];
        int p = atomicAdd(&g_cnt[gi][c], 1);
        g_src[gi][p] = r;
        if (HASW) g_wh[p] = ea[i];
    }
}

__global__ void k_dinv() {
    int i = blockIdx.x * blockDim.x + threadIdx.x;
    if (i < NN) {
        int dg = g_ptr[0][i + 1] - g_ptr[0][i];
        g_dinv_gg[i] = (dg > 0) ? rsqrtf((float)dg) : 0.f;
        int ds = g_ptr[3][i + 1] - g_ptr[3][i];
        g_dinv_ss[i] = (ds > 0) ? rsqrtf((float)ds) : 0.f;
    }
}

// ---------------- TAG1 (5-dim, padded to 8) ----------------
__global__ void k_pad(const float* __restrict__ x) {
    int i = blockIdx.x * blockDim.x + threadIdx.x;
    if (i < NN) {
        const float* r = x + (size_t)i * 5;
        size_t o = (size_t)i * 8;
        *(float4*)(g_x8a + o)     = make_float4(r[0], r[1], r[2], r[3]);
        *(float4*)(g_x8a + o + 4) = make_float4(r[4], 0.f, 0.f, 0.f);
    }
}

__global__ void k_hop5(int in_i, int out_i) {
    const float* __restrict__ x8 = pick8(in_i);
    float* __restrict__ y8 = pick8w(out_i);
    int d = blockIdx.x * blockDim.x + threadIdx.x;
    if (d >= NN) return;
    int beg = g_ptr[0][d], end = g_ptr[0][d + 1];
    float a0 = 0, a1 = 0, a2 = 0, a3 = 0, a4 = 0;
    for (int e = beg; e < end; e++) {
        int s = g_src[0][e];
        float w = g_dinv_gg[s];
        size_t o = (size_t)s * 8;
        float4 v = *(const float4*)(x8 + o);
        float v4 = x8[o + 4];
        a0 = fmaf(w, v.x, a0); a1 = fmaf(w, v.y, a1);
        a2 = fmaf(w, v.z, a2); a3 = fmaf(w, v.w, a3);
        a4 = fmaf(w, v4, a4);
    }
    float sd = g_dinv_gg[d];
    size_t o = (size_t)d * 8;
    *(float4*)(y8 + o)     = make_float4(a0 * sd, a1 * sd, a2 * sd, a3 * sd);
    *(float4*)(y8 + o + 4) = make_float4(a4 * sd, 0.f, 0.f, 0.f);
}

// gx = relu(x8a@W0 + x8b@W1 + x8c@W2 + b); W is (3,5,64)
__global__ void k_tag1(const float* __restrict__ W, const float* __restrict__ b) {
    __shared__ __align__(16) float sW[960];
    __shared__ __align__(16) float sb[64];
    __shared__ __align__(16) float sx[8][16];
    int tid = threadIdx.x;
    for (int i = tid; i < 960; i += 256) sW[i] = W[i];
    if (tid < 64) sb[tid] = b[tid];
    int ni = tid >> 5, tc = tid & 31;
    size_t node = (size_t)blockIdx.x * 8 + ni;
    if (tc < 5)       sx[ni][tc] = g_x8a[node * 8 + tc];
    else if (tc < 10) sx[ni][tc] = g_x8b[node * 8 + (tc - 5)];
    else if (tc < 15) sx[ni][tc] = g_x8c[node * 8 + (tc - 10)];
    __syncthreads();
    int c0 = 2 * tc;
    ull acc = pack2(sb[c0], sb[c0 + 1]);
#pragma unroll
    for (int k = 0; k < 3; k++)
#pragma unroll
        for (int i = 0; i < 5; i++) {
            float xv = sx[ni][k * 5 + i];
            ull w = *(const ull*)&sW[(k * 5 + i) * 64 + c0];
            acc = ffma2(pack2(xv, xv), w, acc);
        }
    float a0, a1; unpack2(acc, a0, a1);
    *(float2*)&g_gx[node * 64 + c0] = make_float2(fmaxf(a0, 0.f), fmaxf(a1, 0.f));
}

// ---------------- 64-dim hop (warp per dst) ----------------
template <int MODE>
__global__ void k_hop64(int in_i, int out_i, int gi) {
    const float* __restrict__ x = pick64(in_i);
    float* __restrict__ y = pick64w(out_i);
    int wid = (blockIdx.x * blockDim.x + threadIdx.x) >> 5;
    if (wid >= NN) return;
    int lane = threadIdx.x & 31;
    int beg = g_ptr[gi][wid], end = g_ptr[gi][wid + 1];
    float a0 = 0.f, a1 = 0.f;
    for (int e = beg; e < end; e++) {
        int s = g_src[gi][e];
        float w;
        if (MODE == 0)      w = g_wh[e];
        else if (MODE == 2) w = g_dinv_ss[s];
        else                w = 1.f;
        size_t o = (size_t)s * 64 + lane;
        a0 = fmaf(w, __ldg(x + o), a0);
        a1 = fmaf(w, __ldg(x + o + 32), a1);
    }
    float sc = 1.f;
    if (MODE == 1) { int c = end - beg; if (c > 0) sc = 1.f / (float)c; }
    if (MODE == 2) sc = g_dinv_ss[wid];
    y[(size_t)wid * 64 + lane]      = a0 * sc;
    y[(size_t)wid * 64 + 32 + lane] = a1 * sc;
}

// ============ register-blocked combines: 32 nodes/block, 4 nodes x 2 cols/thread ============

// s0 = relu(g_agg@w_rel + b_rel + x_state@w_root)
__global__ void k_gc(const float* __restrict__ xs, const float* __restrict__ wrel,
                     const float* __restrict__ brel, const float* __restrict__ wroot) {
    __shared__ __align__(16) float sW[4096];
    __shared__ __align__(16) float sWo[384];
    __shared__ __align__(16) float sb[64];
    __shared__ __align__(16) float sx[2048];   // 32 nodes x 64
    __shared__ __align__(16) float sxs[192];   // 32 nodes x 6
    int tid = threadIdx.x;
    size_t base = (size_t)blockIdx.x * 2048;
    for (int i = tid; i < 4096; i += 256) sW[i] = wrel[i];
    for (int i = tid; i < 384; i += 256) sWo[i] = wroot[i];
    for (int i = tid; i < 2048; i += 256) sx[i] = g_agg[base + i];
    for (int i = tid; i < 192; i += 256) sxs[i] = xs[(size_t)blockIdx.x * 192 + i];
    if (tid < 64) sb[tid] = brel[tid];
    __syncthreads();
    int tc = tid & 31, g = tid >> 5;
    int c0 = 2 * tc;
    ull bias = pack2(sb[c0], sb[c0 + 1]);
    ull acc0 = bias, acc1 = bias, acc2 = bias, acc3 = bias;
    int nb = g * 4;
#pragma unroll 8
    for (int j = 0; j < 64; j++) {
        ull w = *(const ull*)&sW[j * 64 + c0];
        acc0 = ffma2(pack2(sx[(nb + 0) * 64 + j], sx[(nb + 0) * 64 + j]), w, acc0);
        acc1 = ffma2(pack2(sx[(nb + 1) * 64 + j], sx[(nb + 1) * 64 + j]), w, acc1);
        acc2 = ffma2(pack2(sx[(nb + 2) * 64 + j], sx[(nb + 2) * 64 + j]), w, acc2);
        acc3 = ffma2(pack2(sx[(nb + 3) * 64 + j], sx[(nb + 3) * 64 + j]), w, acc3);
    }
#pragma unroll
    for (int j = 0; j < 6; j++) {
        ull w = *(const ull*)&sWo[j * 64 + c0];
        acc0 = ffma2(pack2(sxs[(nb + 0) * 6 + j], sxs[(nb + 0) * 6 + j]), w, acc0);
        acc1 = ffma2(pack2(sxs[(nb + 1) * 6 + j], sxs[(nb + 1) * 6 + j]), w, acc1);
        acc2 = ffma2(pack2(sxs[(nb + 2) * 6 + j], sxs[(nb + 2) * 6 + j]), w, acc2);
        acc3 = ffma2(pack2(sxs[(nb + 3) * 6 + j], sxs[(nb + 3) * 6 + j]), w, acc3);
    }
    size_t nbase = (size_t)blockIdx.x * 32 + nb;
    ull accs[4] = { acc0, acc1, acc2, acc3 };
#pragma unroll
    for (int m = 0; m < 4; m++) {
        float a0, a1; unpack2(accs[m], a0, a1);
        *(float2*)&g_s0[(nbase + m) * 64 + c0] = make_float2(fmaxf(a0, 0.f), fmaxf(a1, 0.f));
    }
}

// s0 = relu(g_agg@w_l + b_l + s0@w_r)
__global__ void k_sage(const float* __restrict__ wl, const float* __restrict__ bl,
                       const float* __restrict__ wr) {
    __shared__ __align__(16) float sW[4096];
    __shared__ __align__(16) float sb[64];
    __shared__ __align__(16) float sm[2048];
    __shared__ __align__(16) float ss[2048];
    int tid = threadIdx.x;
    size_t base = (size_t)blockIdx.x * 2048;
    for (int i = tid; i < 2048; i += 256) { sm[i] = g_agg[base + i]; ss[i] = g_s0[base + i]; }
    for (int i = tid; i < 4096; i += 256) sW[i] = wl[i];
    if (tid < 64) sb[tid] = bl[tid];
    __syncthreads();
    int tc = tid & 31, g = tid >> 5;
    int c0 = 2 * tc;
    int nb = g * 4;
    ull bias = pack2(sb[c0], sb[c0 + 1]);
    ull acc0 = bias, acc1 = bias, acc2 = bias, acc3 = bias;
#pragma unroll 8
    for (int j = 0; j < 64; j++) {
        ull w = *(const ull*)&sW[j * 64 + c0];
        acc0 = ffma2(pack2(sm[(nb + 0) * 64 + j], sm[(nb + 0) * 64 + j]), w, acc0);
        acc1 = ffma2(pack2(sm[(nb + 1) * 64 + j], sm[(nb + 1) * 64 + j]), w, acc1);
        acc2 = ffma2(pack2(sm[(nb + 2) * 64 + j], sm[(nb + 2) * 64 + j]), w, acc2);
        acc3 = ffma2(pack2(sm[(nb + 3) * 64 + j], sm[(nb + 3) * 64 + j]), w, acc3);
    }
    __syncthreads();   // done with sW (wl)
    for (int i = tid; i < 4096; i += 256) sW[i] = wr[i];
    __syncthreads();
#pragma unroll 8
    for (int j = 0; j < 64; j++) {
        ull w = *(const ull*)&sW[j * 64 + c0];
        acc0 = ffma2(pack2(ss[(nb + 0) * 64 + j], ss[(nb + 0) * 64 + j]), w, acc0);
        acc1 = ffma2(pack2(ss[(nb + 1) * 64 + j], ss[(nb + 1) * 64 + j]), w, acc1);
        acc2 = ffma2(pack2(ss[(nb + 2) * 64 + j], ss[(nb + 2) * 64 + j]), w, acc2);
        acc3 = ffma2(pack2(ss[(nb + 3) * 64 + j], ss[(nb + 3) * 64 + j]), w, acc3);
    }
    size_t nbase = (size_t)blockIdx.x * 32 + nb;
    ull accs[4] = { acc0, acc1, acc2, acc3 };
#pragma unroll
    for (int m = 0; m < 4; m++) {
        float a0, a1; unpack2(accs[m], a0, a1);
        *(float2*)&g_s0[(nbase + m) * 64 + c0] = make_float2(fmaxf(a0, 0.f), fmaxf(a1, 0.f));
    }
}

// t = relu(s0@W0 + s1@W1 + s2@W2 + s3@W3 + b);  out = t@lin_w + lin_b
__global__ void k_tag2(const float* __restrict__ W, const float* __restrict__ b,
                       const float* __restrict__ lw, const float* __restrict__ lb,
                       float* __restrict__ out) {
    __shared__ __align__(16) float sW[4096];
    __shared__ __align__(16) float sx[2048];
    __shared__ __align__(16) float st[2048];
    __shared__ __align__(16) float sLin[512];
    __shared__ __align__(16) float sb[64];
    __shared__ __align__(16) float slb[8];
    int tid = threadIdx.x;
    for (int i = tid; i < 512; i += 256) sLin[i] = lw[i];
    if (tid < 64) sb[tid] = b[tid];
    if (tid < 8) slb[tid] = lb[tid];
    __syncthreads();
    int tc = tid & 31, g = tid >> 5;
    int c0 = 2 * tc;
    int nb = g * 4;
    size_t base = (size_t)blockIdx.x * 2048;
    ull bias = pack2(sb[c0], sb[c0 + 1]);
    ull acc0 = bias, acc1 = bias, acc2 = bias, acc3 = bias;
#pragma unroll
    for (int stage = 0; stage < 4; stage++) {
        __syncthreads();   // prior sW/sx use complete
        const float* Sk = (stage == 0) ? g_s0 : (stage == 1) ? g_s1
                         : (stage == 2) ? g_s2 : g_s3;
        for (int i = tid; i < 2048; i += 256) sx[i] = Sk[base + i];
        for (int i = tid; i < 4096; i += 256) sW[i] = W[stage * 4096 + i];
        __syncthreads();
#pragma unroll 8
        for (int j = 0; j < 64; j++) {
            ull w = *(const ull*)&sW[j * 64 + c0];
            acc0 = ffma2(pack2(sx[(nb + 0) * 64 + j], sx[(nb + 0) * 64 + j]), w, acc0);
            acc1 = ffma2(pack2(sx[(nb + 1) * 64 + j], sx[(nb + 1) * 64 + j]), w, acc1);
            acc2 = ffma2(pack2(sx[(nb + 2) * 64 + j], sx[(nb + 2) * 64 + j]), w, acc2);
            acc3 = ffma2(pack2(sx[(nb + 3) * 64 + j], sx[(nb + 3) * 64 + j]), w, acc3);
        }
    }
    ull accs[4] = { acc0, acc1, acc2, acc3 };
#pragma unroll
    for (int m = 0; m < 4; m++) {
        float a0, a1; unpack2(accs[m], a0, a1);
        st[(nb + m) * 64 + c0]     = fmaxf(a0, 0.f);
        st[(nb + m) * 64 + c0 + 1] = fmaxf(a1, 0.f);
    }
    __syncthreads();
    // final Linear: 32 nodes x 8 cols = 256 outputs, one per thread
    int n = tid >> 3, o = tid & 7;
    float acc = slb[o];
#pragma unroll 8
    for (int j = 0; j < 64; j++) acc = fmaf(st[n * 64 + j], sLin[j * 8 + o], acc);
    out[((size_t)blockIdx.x * 32 + n) * 8 + o] = acc;
}

// ---------------- host launch (kernel launches ONLY) ----------------
extern "C" void kernel_launch(void* const* d_in, const int* in_sizes, int n_in,
                              void* d_out, int out_size) {
    const float* x_game     = (const float*)d_in[0];
    const float* x_state    = (const float*)d_in[1];
    const int* e_gg         = (const int*)d_in[2];
    const int* e_hist       = (const int*)d_in[3];
    const int* e_in         = (const int*)d_in[4];
    const int* e_ss         = (const int*)d_in[5];
    const float* ea_hist    = (const float*)d_in[6];
    const float* tag1_w     = (const float*)d_in[7];
    const float* tag1_b     = (const float*)d_in[8];
    const float* tag2_w     = (const float*)d_in[9];
    const float* tag2_b     = (const float*)d_in[10];
    const float* gc_w_rel   = (const float*)d_in[11];
    const float* gc_b_rel   = (const float*)d_in[12];
    const float* gc_w_root  = (const float*)d_in[13];
    const float* sage_w_l   = (const float*)d_in[14];
    const float* sage_b_l   = (const float*)d_in[15];
    const float* sage_w_r   = (const float*)d_in[16];
    const float* lin_w      = (const float*)d_in[17];
    const float* lin_b      = (const float*)d_in[18];

    int E[4] = { in_sizes[2] / 2, in_sizes[3] / 2, in_sizes[4] / 2, in_sizes[5] / 2 };
    const int* EI[4] = { e_gg, e_hist, e_in, e_ss };

    // ---- CSR build ----
    k_zero_deg<<<(4 * NN + 255) / 256, 256>>>();
    for (int i = 0; i < 4; i++)
        k_count<<<(E[i] + 255) / 256, 256>>>(EI[i], E[i], i);
    for (int i = 0; i < 4; i++) {
        k_scan1<<<SCAN_NB, SCAN_BS>>>(i);
        k_scan2<<<1, SCAN_NB>>>(i);
        k_scan3<<<SCAN_NB, SCAN_BS>>>(i, E[i]);
    }
    k_fill<0><<<(E[0] + 255) / 256, 256>>>(EI[0], E[0], 0, nullptr);
    k_fill<1><<<(E[1] + 255) / 256, 256>>>(EI[1], E[1], 1, ea_hist);
    k_fill<0><<<(E[2] + 255) / 256, 256>>>(EI[2], E[2], 2, nullptr);
    k_fill<0><<<(E[3] + 255) / 256, 256>>>(EI[3], E[3], 3, nullptr);
    k_dinv<<<(NN + 255) / 256, 256>>>();

    // ---- TAGConv1 (game graph, 5-dim propagation) ----
    k_pad<<<(NN + 255) / 256, 256>>>(x_game);
    k_hop5<<<(NN + 255) / 256, 256>>>(0, 1);   // x8a -> x8b
    k_hop5<<<(NN + 255) / 256, 256>>>(1, 2);   // x8b -> x8c
    k_tag1<<<NN / 8, 256>>>(tag1_w, tag1_b);

    // ---- GraphConv (hist, weighted) ----
    k_hop64<0><<<NN / 8, 256>>>(3, 4, 1);      // gx -> agg
    k_gc<<<NN / 32, 256>>>(x_state, gc_w_rel, gc_b_rel, gc_w_root);

    // ---- SAGEConv (in, mean) ----
    k_hop64<1><<<NN / 8, 256>>>(3, 4, 2);      // gx -> agg
    k_sage<<<NN / 32, 256>>>(sage_w_l, sage_b_l, sage_w_r);

    // ---- TAGConv2 (ss, 3 normalized hops) + fused final Linear ----
    k_hop64<2><<<NN / 8, 256>>>(5, 6, 3);      // s0 -> s1
    k_hop64<2><<<NN / 8, 256>>>(6, 7, 3);      // s1 -> s2
    k_hop64<2><<<NN / 8, 256>>>(7, 8, 3);      // s2 -> s3
    k_tag2<<<NN / 32, 256>>>(tag2_w, tag2_b, lin_w, lin_b, (float*)d_out);
}